// round 11
// baseline (speedup 1.0000x reference)
#include <cuda_runtime.h>
#include <cuda_bf16.h>
#include <cstdint>

// Problem constants
#define B_      1024
#define T_      120
#define E_      50
#define H_      300
#define C_      5
#define G_      1200
#define VOCAB_  50000

// Logical K layout: k 0..49 = x, 50..51 = zero gap, 52..351 = h  -> K = 352
#define KTOT    352
#define KH      176           // elements per half
#define KROWB   368           // bytes per SMEM row (184 elems, 8 pad) - bank-conflict-free stride
#define NKC     11            // k16 chunks per half

#define NBB     8
#define BR      128           // batch rows per CTA (M)
#define NSL     15
#define HC      20            // h cols per CTA
#define GC      80            // gate cols per CTA (N)
#define NCTA    120
#define THREADS 128
#define XROW    52            // padded g_x row (50 + 2 zeros)

// SMEM offsets (bytes from 1024-aligned base)
#define OFF_AHI 0u                         // A hi plane: 128*368 = 47104
#define OFF_ALO 47104u
#define OFF_W   94208u                     // 4 planes of 80*368: WH half0, WH half1, WL half0, WL half1
#define WPLANE  29440u
#define OFF_BIAS 211968u
#define SMEM_TOTAL (212288 + 1024)

typedef unsigned u32;

// ---------------------------------------------------------------- scratch
__device__ u32   g_hs[(size_t)(T_+1) * B_ * H_];   // [t][b][h], packed (bf16 hi | bf16 lo<<16)
__device__ u32   g_x [(size_t)T_ * B_ * XROW];     // [t][b][52], packed split embeddings
__device__ float g_partial_ce[T_];
__device__ float g_partial_cnt[T_];
__device__ u32   g_count;

// ---------------------------------------------------------------- helpers
__device__ __forceinline__ float sigf(float x)  { return __fdividef(1.0f, 1.0f + __expf(-x)); }
__device__ __forceinline__ float tanh_f(float x){ return 2.0f * sigf(2.0f * x) - 1.0f; }

__device__ __forceinline__ u32 splitpack(float v) {
    __nv_bfloat16 h = __float2bfloat16(v);
    float fh = __bfloat162float(h);
    __nv_bfloat16 l = __float2bfloat16(v - fh);
    return (u32)__bfloat16_as_ushort(h) | ((u32)__bfloat16_as_ushort(l) << 16);
}
__device__ __forceinline__ float unpackf(u32 u) {
    return __bfloat162float(__ushort_as_bfloat16((unsigned short)(u & 0xFFFFu)))
         + __bfloat162float(__ushort_as_bfloat16((unsigned short)(u >> 16)));
}
// swizzled byte offset within a plane: row r, row-local byte kb
__device__ __forceinline__ u32 swz(u32 r, u32 kb) {
    return r * KROWB + (kb ^ (((r >> 3) & 3u) << 4));
}
__device__ __forceinline__ void mma_bf16(float& d0, float& d1, float& d2, float& d3,
                                         u32 a0, u32 a1, u32 a2, u32 a3, u32 b0, u32 b1) {
    asm("mma.sync.aligned.m16n8k16.row.col.f32.bf16.bf16.f32 "
        "{%0,%1,%2,%3}, {%4,%5,%6,%7}, {%8,%9}, {%0,%1,%2,%3};"
        : "+f"(d0), "+f"(d1), "+f"(d2), "+f"(d3)
        : "r"(a0), "r"(a1), "r"(a2), "r"(a3), "r"(b0), "r"(b1));
}

// ---------------------------------------------------------------- init / precompute
__global__ void init_kernel() {
    int idx = blockIdx.x * blockDim.x + threadIdx.x;
    if (idx < B_ * H_) g_hs[idx] = 0u;          // h0 = 0 (packed zero)
    if (idx == 0) g_count = 0u;
}

__global__ void __launch_bounds__(256)
prex_kernel(const int* __restrict__ tokens, const float* __restrict__ emb) {
    int idx = blockIdx.x * 256 + threadIdx.x;
    if (idx >= T_ * B_) return;
    int b = idx % B_, t = idx / B_;
    const float* er = emb + (size_t)tokens[b * T_ + t] * E_;
    u32* dst = g_x + ((size_t)t * B_ + b) * XROW;
    #pragma unroll 5
    for (int e = 0; e < E_; ++e) dst[e] = splitpack(er[e]);
    dst[50] = 0u; dst[51] = 0u;
}

// ---------------------------------------------------------------- main LSTM (HMMA bf16x3)
__global__ void __launch_bounds__(THREADS, 1)
lstm_main(const float* __restrict__ Wx, const float* __restrict__ Wh,
          const float* __restrict__ bias)
{
    extern __shared__ char smem_raw[];
    char* sm = (char*)(((uintptr_t)smem_raw + 1023) & ~(uintptr_t)1023);
    float* bias_sm = (float*)(sm + OFF_BIAS);

    const int tid  = threadIdx.x;
    const int wid  = tid >> 5;
    const int lane = tid & 31;
    const int g    = lane >> 2;      // mma group row 0..7
    const int tg   = lane & 3;       // thread-in-group 0..3
    const int R0   = wid * 32;       // warp's row base
    const int bb   = blockIdx.x / NSL;
    const int sl   = blockIdx.x % NSL;
    const int b0   = bb * BR;
    const int h0   = sl * HC;
    const int r    = tid;            // this thread stages batch row b0 + r

    // ---- one-time: W hi/lo tiles (per K-half planes), swizzled
    for (int half = 0; half < 2; ++half) {
        char* WHp = sm + OFF_W + (u32)half * WPLANE;
        char* WLp = sm + OFF_W + 2u * WPLANE + (u32)half * WPLANE;
        for (int idx = tid; idx < GC * 184; idx += THREADS) {
            int n = idx / 184, ke = idx % 184;
            int k = half * KH + ke;
            float v = 0.0f;
            if (ke < KH) {
                int col = (n & 3) * H_ + h0 + (n >> 2);
                if (k < 50)                 v = Wx[k * G_ + col];
                else if (k >= 52 && k < KTOT) v = Wh[(k - 52) * G_ + col];
            }
            u32 pk = splitpack(v);
            u32 off = swz((u32)n, (u32)ke * 2u);
            *(unsigned short*)(WHp + off) = (unsigned short)(pk & 0xFFFFu);
            *(unsigned short*)(WLp + off) = (unsigned short)(pk >> 16);
        }
    }
    for (int n = tid; n < GC; n += THREADS)
        bias_sm[n] = bias[(n & 3) * H_ + h0 + (n >> 2)];
    __syncthreads();

    float cst[2][10];
    #pragma unroll
    for (int mt = 0; mt < 2; ++mt)
        #pragma unroll
        for (int nt = 0; nt < 10; ++nt) cst[mt][nt] = 0.0f;

    for (int t = 0; t < T_; ++t) {
        const u32* xrow = g_x  + ((size_t)t * B_ + b0 + r) * XROW;
        const u32* hrow = g_hs + ((size_t)t * B_ + b0 + r) * H_;

        // accumulators = bias
        float d[2][10][4];
        #pragma unroll
        for (int nt = 0; nt < 10; ++nt) {
            float bv0 = bias_sm[nt * 8 + 2 * tg];
            float bv1 = bias_sm[nt * 8 + 2 * tg + 1];
            #pragma unroll
            for (int mt = 0; mt < 2; ++mt) {
                d[mt][nt][0] = bv0; d[mt][nt][1] = bv1;
                d[mt][nt][2] = bv0; d[mt][nt][3] = bv1;
            }
        }

        #pragma unroll 1
        for (int half = 0; half < 2; ++half) {
            // ---- stage A hi/lo for this half (thread = its own row; all uint4 aligned)
            #pragma unroll 4
            for (int s = 0; s < 44; ++s) {
                uint4 v;
                if (half == 0) v = (s < 13) ? __ldg ((const uint4*)(xrow + 4 * s))
                                            : __ldcg((const uint4*)(hrow + 4 * (s - 13)));
                else           v = __ldcg((const uint4*)(hrow + 124 + 4 * s));
                u32 h01 = (v.x & 0xFFFFu) | (v.y << 16);
                u32 h23 = (v.z & 0xFFFFu) | (v.w << 16);
                u32 l01 = (v.x >> 16) | (v.y & 0xFFFF0000u);
                u32 l23 = (v.z >> 16) | (v.w & 0xFFFF0000u);
                u32 off = swz((u32)r, (u32)s * 8u);
                *(uint2*)(sm + OFF_AHI + off) = make_uint2(h01, h23);
                *(uint2*)(sm + OFF_ALO + off) = make_uint2(l01, l23);
            }
            __syncthreads();

            const char* WHp = sm + OFF_W + (u32)half * WPLANE;
            const char* WLp = sm + OFF_W + 2u * WPLANE + (u32)half * WPLANE;

            #pragma unroll 1
            for (int kc = 0; kc < NKC; ++kc) {
                const u32 cb = (u32)(kc * 32 + 4 * tg);
                u32 ah[2][4], al[2][4];
                #pragma unroll
                for (int mt = 0; mt < 2; ++mt) {
                    u32 ra = (u32)(R0 + mt * 16 + g), rb = ra + 8u;
                    u32 oa0 = swz(ra, cb),       ob0 = swz(rb, cb);
                    u32 oa1 = swz(ra, cb + 16u), ob1 = swz(rb, cb + 16u);
                    ah[mt][0] = *(const u32*)(sm + OFF_AHI + oa0);
                    ah[mt][1] = *(const u32*)(sm + OFF_AHI + ob0);
                    ah[mt][2] = *(const u32*)(sm + OFF_AHI + oa1);
                    ah[mt][3] = *(const u32*)(sm + OFF_AHI + ob1);
                    al[mt][0] = *(const u32*)(sm + OFF_ALO + oa0);
                    al[mt][1] = *(const u32*)(sm + OFF_ALO + ob0);
                    al[mt][2] = *(const u32*)(sm + OFF_ALO + oa1);
                    al[mt][3] = *(const u32*)(sm + OFF_ALO + ob1);
                }
                #pragma unroll
                for (int nt = 0; nt < 10; ++nt) {
                    u32 na = (u32)(nt * 8 + g);
                    u32 o0 = swz(na, cb), o1 = swz(na, cb + 16u);
                    u32 bh0 = *(const u32*)(WHp + o0), bh1 = *(const u32*)(WHp + o1);
                    u32 bl0 = *(const u32*)(WLp + o0), bl1 = *(const u32*)(WLp + o1);
                    #pragma unroll
                    for (int mt = 0; mt < 2; ++mt) {
                        mma_bf16(d[mt][nt][0], d[mt][nt][1], d[mt][nt][2], d[mt][nt][3],
                                 ah[mt][0], ah[mt][1], ah[mt][2], ah[mt][3], bh0, bh1);
                        mma_bf16(d[mt][nt][0], d[mt][nt][1], d[mt][nt][2], d[mt][nt][3],
                                 ah[mt][0], ah[mt][1], ah[mt][2], ah[mt][3], bl0, bl1);
                        mma_bf16(d[mt][nt][0], d[mt][nt][1], d[mt][nt][2], d[mt][nt][3],
                                 al[mt][0], al[mt][1], al[mt][2], al[mt][3], bh0, bh1);
                    }
                }
            }
            __syncthreads();   // protect A before next staging / next step
        }

        // ---- epilogue: pair-exchange gates, LSTM cell, write packed h
        const int  odd = lane & 1;
        u32* hbase = g_hs + (size_t)(t + 1) * B_ * H_;
        #pragma unroll
        for (int mt = 0; mt < 2; ++mt) {
            #pragma unroll
            for (int nt = 0; nt < 10; ++nt) {
                float e0 = __shfl_xor_sync(0xffffffffu, d[mt][nt][0], 1);
                float e1 = __shfl_xor_sync(0xffffffffu, d[mt][nt][1], 1);
                float e2 = __shfl_xor_sync(0xffffffffu, d[mt][nt][2], 1);
                float e3 = __shfl_xor_sync(0xffffffffu, d[mt][nt][3], 1);
                float zi, zj, zf, zo; int row;
                if (!odd) { zi = d[mt][nt][0]; zj = d[mt][nt][1]; zf = e0; zo = e1;
                            row = R0 + mt * 16 + g; }
                else      { zi = e2; zj = e3; zf = d[mt][nt][2]; zo = d[mt][nt][3];
                            row = R0 + mt * 16 + g + 8; }
                float ig = sigf(zi);
                float jg = tanh_f(zj);
                float fg = sigf(zf + 1.0f);      // FORGET_BIAS
                float og = sigf(zo);
                float cn = fg * cst[mt][nt] + ig * jg;
                cst[mt][nt] = cn;
                float hn = og * tanh_f(cn);
                int h = h0 + nt * 2 + (tg >> 1);
                hbase[(size_t)(b0 + row) * H_ + h] = splitpack(hn);
            }
        }

        // ---- grid barrier (120 co-resident CTAs, monotonic ticket)
        if (t + 1 < T_) {
            __threadfence();
            __syncthreads();
            if (tid == 0) {
                atomicAdd(&g_count, 1u);
                const u32 target = (u32)(t + 1) * NCTA;
                while (*(volatile u32*)&g_count < target) __nanosleep(64);
                __threadfence();
            }
            __syncthreads();
        }
    }
}

// ---------------------------------------------------------------- CE loss
__global__ void __launch_bounds__(256)
ce_kernel(const int* __restrict__ labels, const void* __restrict__ maskp,
          const float* __restrict__ U, const float* __restrict__ b2)
{
    __shared__ float Us[H_ * C_];
    __shared__ float b2s[C_];
    __shared__ u32   flg_s[8];
    __shared__ float redce[8], redm[8];

    const int t = blockIdx.x;
    const int tid = threadIdx.x;
    const int lane = tid & 31, wid = tid >> 5;

    for (int i = tid; i < H_ * C_; i += 256) Us[i] = U[i];
    if (tid < C_) b2s[tid] = b2[tid];

    const u32* mi = (const u32*)maskp;
    u32 fl = 0;
    for (int i = tid; i < (B_ * T_) / 4; i += 256) {
        u32 v = mi[i];
        if (v & ~1u)                     fl |= 1;
        if (v != 0u && v != 0x3F800000u) fl |= 2;
        if (v & 0xFEFEFEFEu)             fl |= 4;
    }
    #pragma unroll
    for (int off = 16; off; off >>= 1) fl |= __shfl_down_sync(0xffffffffu, fl, off);
    if (lane == 0) flg_s[wid] = fl;
    __syncthreads();
    if (tid == 0) { u32 a = 0; for (int w = 0; w < 8; ++w) a |= flg_s[w]; flg_s[0] = a; }
    __syncthreads();
    fl = flg_s[0];
    const int mode = (!(fl & 1)) ? 0 : ((!(fl & 4)) ? 1 : ((!(fl & 2)) ? 2 : 0));

    float sce = 0.0f, smv = 0.0f;
    for (int b = tid; b < B_; b += 256) {
        float acc[C_];
        #pragma unroll
        for (int c = 0; c < C_; ++c) acc[c] = b2s[c];
        const u32* hp = g_hs + ((size_t)(t + 1) * B_ + b) * H_;
        #pragma unroll 4
        for (int h = 0; h < H_; ++h) {
            float v = unpackf(hp[h]);
            #pragma unroll
            for (int c = 0; c < C_; ++c) acc[c] += v * Us[h * C_ + c];
        }
        float mx = acc[0];
        #pragma unroll
        for (int c = 1; c < C_; ++c) mx = fmaxf(mx, acc[c]);
        float s = 0.0f;
        #pragma unroll
        for (int c = 0; c < C_; ++c) s += __expf(acc[c] - mx);
        float lse = mx + __logf(s);
        int lab = labels[b * T_ + t];
        lab = max(0, min(C_ - 1, lab));
        float ce = lse - acc[lab];

        const int j = b * T_ + t;
        float mk;
        if (mode == 0)      mk = ((const int*)maskp)[j] ? 1.0f : 0.0f;
        else if (mode == 1) mk = ((const unsigned char*)maskp)[j] ? 1.0f : 0.0f;
        else                mk = (((const float*)maskp)[j] != 0.0f) ? 1.0f : 0.0f;
        sce += ce * mk;
        smv += mk;
    }
    #pragma unroll
    for (int off = 16; off; off >>= 1) {
        sce += __shfl_down_sync(0xffffffffu, sce, off);
        smv += __shfl_down_sync(0xffffffffu, smv, off);
    }
    if (lane == 0) { redce[wid] = sce; redm[wid] = smv; }
    __syncthreads();
    if (tid == 0) {
        float a = 0.0f, c = 0.0f;
        for (int w = 0; w < 8; ++w) { a += redce[w]; c += redm[w]; }
        g_partial_ce[t] = a;
        g_partial_cnt[t] = c;
    }
}

__global__ void fin_kernel(float* out) {
    float a = 0.0f, c = 0.0f;
    for (int t = 0; t < T_; ++t) { a += g_partial_ce[t]; c += g_partial_cnt[t]; }
    out[0] = a / c;
}

// ---------------------------------------------------------------- launch
extern "C" void kernel_launch(void* const* d_in, const int* in_sizes, int n_in,
                              void* d_out, int out_size)
{
    cudaFuncSetAttribute(lstm_main, cudaFuncAttributeMaxDynamicSharedMemorySize, SMEM_TOTAL);

    const int*   tokens = (const int*)  d_in[0];
    const int*   labels = (const int*)  d_in[1];
    const void*  mask   =               d_in[2];
    const float* emb    = (const float*)d_in[3];
    const float* Wx     = (const float*)d_in[4];
    const float* Wh     = (const float*)d_in[5];
    const float* b      = (const float*)d_in[6];
    const float* U      = (const float*)d_in[7];
    const float* b2     = (const float*)d_in[8];
    float*       out    = (float*)d_out;

    init_kernel<<<(B_ * H_ + 1023) / 1024, 1024>>>();
    prex_kernel<<<(T_ * B_ + 255) / 256, 256>>>(tokens, emb);
    lstm_main<<<NCTA, THREADS, SMEM_TOTAL>>>(Wx, Wh, b);
    ce_kernel<<<T_, 256>>>(labels, mask, U, b2);
    fin_kernel<<<1, 1>>>(out);
}

// round 13
// speedup vs baseline: 1.9061x; 1.9061x over previous
#include <cuda_runtime.h>
#include <cuda_bf16.h>
#include <cstdint>

// Problem constants
#define B_      1024
#define T_      120
#define E_      50
#define H_      300
#define C_      5
#define G_      1200
#define VOCAB_  50000

// Combined input row per (t,b): [0..49]=x, [50..51]=0, [52..351]=h  -> 352 elems
#define KTOT    352
#define KH      176           // elements per half
#define KROWB   368           // SMEM row stride bytes
#define NKC     11            // k16 chunks per half
#define ROWE    352           // global row elems (704 B, 16B aligned)

#define NBB     8
#define BR      128           // batch rows per CTA (M)
#define NSL     15
#define HC      20            // h cols per CTA
#define GC      80            // gate cols per CTA (N)
#define NCTA    120
#define THREADS 256

// SMEM offsets (bytes from 1024-aligned base)
#define OFF_AHI 0u
#define OFF_ALO 47104u
#define OFF_W   94208u        // 4 planes of 80*368: WH h0, WH h1, WL h0, WL h1
#define WPLANE  29440u
#define OFF_BIAS 211968u
#define SMEM_TOTAL (212288 + 1024)

typedef unsigned u32;

// ---------------------------------------------------------------- scratch
// split-precision planes: value = bf16(hi) + bf16(lo)
__device__ __align__(256) unsigned short g_Ahi[(size_t)(T_+1) * B_ * ROWE];
__device__ __align__(256) unsigned short g_Alo[(size_t)(T_+1) * B_ * ROWE];
__device__ float g_partial_ce[T_];
__device__ float g_partial_cnt[T_];
__device__ u32   g_count;

// ---------------------------------------------------------------- helpers
__device__ __forceinline__ float sigf(float x)  { return __fdividef(1.0f, 1.0f + __expf(-x)); }
__device__ __forceinline__ float tanh_f(float x){ return 2.0f * sigf(2.0f * x) - 1.0f; }

__device__ __forceinline__ u32 splitpack(float v) {
    __nv_bfloat16 h = __float2bfloat16(v);
    float fh = __bfloat162float(h);
    __nv_bfloat16 l = __float2bfloat16(v - fh);
    return (u32)__bfloat16_as_ushort(h) | ((u32)__bfloat16_as_ushort(l) << 16);
}
__device__ __forceinline__ float us2f(unsigned short u) {
    return __bfloat162float(__ushort_as_bfloat16(u));
}
__device__ __forceinline__ u32 smem_u32(const void* p) {
    u32 a; asm("{ .reg .u64 t; cvta.to.shared.u64 t, %1; cvt.u32.u64 %0, t; }" : "=r"(a) : "l"(p));
    return a;
}
// swizzled byte offset within a plane (16B-granule XOR, same as validated R11)
__device__ __forceinline__ u32 swz(u32 r, u32 kb) {
    return r * KROWB + (kb ^ (((r >> 3) & 3u) << 4));
}
__device__ __forceinline__ void cpa16(u32 dst, const void* src) {
    asm volatile("cp.async.cg.shared.global [%0], [%1], 16;"
                 :: "r"(dst), "l"(__cvta_generic_to_global(src)) : "memory");
}
__device__ __forceinline__ void mma_bf16(float& d0, float& d1, float& d2, float& d3,
                                         u32 a0, u32 a1, u32 a2, u32 a3, u32 b0, u32 b1) {
    asm("mma.sync.aligned.m16n8k16.row.col.f32.bf16.bf16.f32 "
        "{%0,%1,%2,%3}, {%4,%5,%6,%7}, {%8,%9}, {%0,%1,%2,%3};"
        : "+f"(d0), "+f"(d1), "+f"(d2), "+f"(d3)
        : "r"(a0), "r"(a1), "r"(a2), "r"(a3), "r"(b0), "r"(b1));
}

// ---------------------------------------------------------------- init / precompute
__global__ void init_kernel() {
    int idx = blockIdx.x * blockDim.x + threadIdx.x;
    if (idx < B_ * H_) {                       // zero h-part of plane 0
        int b = idx / H_, h = idx % H_;
        size_t o = (size_t)b * ROWE + 52 + h;
        g_Ahi[o] = 0; g_Alo[o] = 0;
    }
    if (idx == 0) g_count = 0u;
}

__global__ void __launch_bounds__(256)
prex_kernel(const int* __restrict__ tokens, const float* __restrict__ emb) {
    int idx = blockIdx.x * 256 + threadIdx.x;
    if (idx >= T_ * B_) return;
    int b = idx % B_, t = idx / B_;
    const float* er = emb + (size_t)tokens[b * T_ + t] * E_;
    size_t base = ((size_t)t * B_ + b) * ROWE;
    #pragma unroll 5
    for (int e = 0; e < E_; ++e) {
        u32 pk = splitpack(er[e]);
        g_Ahi[base + e] = (unsigned short)(pk & 0xFFFFu);
        g_Alo[base + e] = (unsigned short)(pk >> 16);
    }
    g_Ahi[base + 50] = 0; g_Ahi[base + 51] = 0;
    g_Alo[base + 50] = 0; g_Alo[base + 51] = 0;
}

// ---------------------------------------------------------------- main LSTM (HMMA bf16x3, 8 warps)
__global__ void __launch_bounds__(THREADS, 1)
lstm_main(const float* __restrict__ Wx, const float* __restrict__ Wh,
          const float* __restrict__ bias)
{
    extern __shared__ char smem_raw[];
    char* sm = (char*)(((uintptr_t)smem_raw + 1023) & ~(uintptr_t)1023);
    const u32 sb = smem_u32(sm);
    float* bias_sm = (float*)(sm + OFF_BIAS);

    const int tid  = threadIdx.x;
    const int wid  = tid >> 5;
    const int lane = tid & 31;
    const int g    = lane >> 2;      // mma group row 0..7
    const int tg   = lane & 3;       // thread-in-group 0..3
    const int rg   = wid & 3;        // row group
    const int nh   = wid >> 2;       // N half (0: cols 0..39, 1: 40..79)
    const int R0   = rg * 32;
    const int bb   = blockIdx.x / NSL;
    const int sl   = blockIdx.x % NSL;
    const int b0   = bb * BR;
    const int h0   = sl * HC;
    const int r    = tid & 127;      // staged batch row b0 + r
    const int p    = tid >> 7;       // chunk half for staging

    // ---- one-time: W hi/lo tiles (per K-half planes), swizzled (verbatim R11)
    for (int half = 0; half < 2; ++half) {
        char* WHp = sm + OFF_W + (u32)half * WPLANE;
        char* WLp = sm + OFF_W + 2u * WPLANE + (u32)half * WPLANE;
        for (int idx = tid; idx < GC * 184; idx += THREADS) {
            int n = idx / 184, ke = idx % 184;
            int k = half * KH + ke;
            float v = 0.0f;
            if (ke < KH) {
                int col = (n & 3) * H_ + h0 + (n >> 2);
                if (k < 50)                   v = Wx[k * G_ + col];
                else if (k >= 52 && k < KTOT) v = Wh[(k - 52) * G_ + col];
            }
            u32 pk = splitpack(v);
            u32 off = swz((u32)n, (u32)ke * 2u);
            *(unsigned short*)(WHp + off) = (unsigned short)(pk & 0xFFFFu);
            *(unsigned short*)(WLp + off) = (unsigned short)(pk >> 16);
        }
    }
    for (int n = tid; n < GC; n += THREADS)
        bias_sm[n] = bias[(n & 3) * H_ + h0 + (n >> 2)];
    __syncthreads();

    float cst[2][5];
    #pragma unroll
    for (int mt = 0; mt < 2; ++mt)
        #pragma unroll
        for (int nt = 0; nt < 5; ++nt) cst[mt][nt] = 0.0f;

    for (int t = 0; t < T_; ++t) {
        const unsigned short* srcHi = g_Ahi + ((size_t)t * B_ + b0 + r) * ROWE;
        const unsigned short* srcLo = g_Alo + ((size_t)t * B_ + b0 + r) * ROWE;

        // accumulators = bias
        float d[2][5][4];
        #pragma unroll
        for (int nt = 0; nt < 5; ++nt) {
            int ntg = nh * 5 + nt;
            float bv0 = bias_sm[ntg * 8 + 2 * tg];
            float bv1 = bias_sm[ntg * 8 + 2 * tg + 1];
            #pragma unroll
            for (int mt = 0; mt < 2; ++mt) {
                d[mt][nt][0] = bv0; d[mt][nt][1] = bv1;
                d[mt][nt][2] = bv0; d[mt][nt][3] = bv1;
            }
        }

        #pragma unroll 1
        for (int half = 0; half < 2; ++half) {
            // ---- stage A hi/lo via cp.async (two threads per row, 11 16B chunks each per plane)
            {
                const unsigned short* sh = srcHi + half * KH;
                const unsigned short* sl2 = srcLo + half * KH;
                #pragma unroll
                for (int j = 0; j < 11; ++j) {
                    int s = p * 11 + j;
                    u32 dsw = swz((u32)r, (u32)s * 16u);
                    cpa16(sb + OFF_AHI + dsw, sh + s * 8);
                    cpa16(sb + OFF_ALO + dsw, sl2 + s * 8);
                }
                asm volatile("cp.async.commit_group;" ::: "memory");
                asm volatile("cp.async.wait_group 0;" ::: "memory");
            }
            __syncthreads();

            const char* WHp = sm + OFF_W + (u32)half * WPLANE;
            const char* WLp = sm + OFF_W + 2u * WPLANE + (u32)half * WPLANE;

            #pragma unroll 1
            for (int kc = 0; kc < NKC; ++kc) {
                const u32 cb = (u32)(kc * 32 + 4 * tg);
                u32 ah[2][4], al[2][4];
                #pragma unroll
                for (int mt = 0; mt < 2; ++mt) {
                    u32 ra = (u32)(R0 + mt * 16 + g), rb = ra + 8u;
                    u32 oa0 = swz(ra, cb),       ob0 = swz(rb, cb);
                    u32 oa1 = swz(ra, cb + 16u), ob1 = swz(rb, cb + 16u);
                    ah[mt][0] = *(const u32*)(sm + OFF_AHI + oa0);
                    ah[mt][1] = *(const u32*)(sm + OFF_AHI + ob0);
                    ah[mt][2] = *(const u32*)(sm + OFF_AHI + oa1);
                    ah[mt][3] = *(const u32*)(sm + OFF_AHI + ob1);
                    al[mt][0] = *(const u32*)(sm + OFF_ALO + oa0);
                    al[mt][1] = *(const u32*)(sm + OFF_ALO + ob0);
                    al[mt][2] = *(const u32*)(sm + OFF_ALO + oa1);
                    al[mt][3] = *(const u32*)(sm + OFF_ALO + ob1);
                }
                #pragma unroll
                for (int nt = 0; nt < 5; ++nt) {
                    u32 na = (u32)((nh * 5 + nt) * 8 + g);
                    u32 o0 = swz(na, cb), o1 = swz(na, cb + 16u);
                    u32 bh0 = *(const u32*)(WHp + o0), bh1 = *(const u32*)(WHp + o1);
                    u32 bl0 = *(const u32*)(WLp + o0), bl1 = *(const u32*)(WLp + o1);
                    #pragma unroll
                    for (int mt = 0; mt < 2; ++mt) {
                        mma_bf16(d[mt][nt][0], d[mt][nt][1], d[mt][nt][2], d[mt][nt][3],
                                 ah[mt][0], ah[mt][1], ah[mt][2], ah[mt][3], bh0, bh1);
                        mma_bf16(d[mt][nt][0], d[mt][nt][1], d[mt][nt][2], d[mt][nt][3],
                                 ah[mt][0], ah[mt][1], ah[mt][2], ah[mt][3], bl0, bl1);
                        mma_bf16(d[mt][nt][0], d[mt][nt][1], d[mt][nt][2], d[mt][nt][3],
                                 al[mt][0], al[mt][1], al[mt][2], al[mt][3], bh0, bh1);
                    }
                }
            }
            __syncthreads();   // all reads done before next staging overwrites A
        }

        // ---- epilogue: pair-exchange gates, LSTM cell, write hi/lo h
        const int odd = lane & 1;
        #pragma unroll
        for (int mt = 0; mt < 2; ++mt) {
            #pragma unroll
            for (int nt = 0; nt < 5; ++nt) {
                int ntg = nh * 5 + nt;
                float e0 = __shfl_xor_sync(0xffffffffu, d[mt][nt][0], 1);
                float e1 = __shfl_xor_sync(0xffffffffu, d[mt][nt][1], 1);
                float e2 = __shfl_xor_sync(0xffffffffu, d[mt][nt][2], 1);
                float e3 = __shfl_xor_sync(0xffffffffu, d[mt][nt][3], 1);
                float zi, zj, zf, zo; int row;
                if (!odd) { zi = d[mt][nt][0]; zj = d[mt][nt][1]; zf = e0; zo = e1;
                            row = R0 + mt * 16 + g; }
                else      { zi = e2; zj = e3; zf = d[mt][nt][2]; zo = d[mt][nt][3];
                            row = R0 + mt * 16 + g + 8; }
                float ig = sigf(zi);
                float jg = tanh_f(zj);
                float fg = sigf(zf + 1.0f);      // FORGET_BIAS
                float og = sigf(zo);
                float cn = fg * cst[mt][nt] + ig * jg;
                cst[mt][nt] = cn;
                float hn = og * tanh_f(cn);
                int hcol = h0 + ntg * 2 + (tg >> 1);
                size_t o = ((size_t)(t + 1) * B_ + b0 + row) * ROWE + 52 + hcol;
                u32 pk = splitpack(hn);
                g_Ahi[o] = (unsigned short)(pk & 0xFFFFu);
                g_Alo[o] = (unsigned short)(pk >> 16);
            }
        }

        // ---- grid barrier (120 co-resident CTAs, monotonic ticket)
        if (t + 1 < T_) {
            __threadfence();
            __syncthreads();
            if (tid == 0) {
                atomicAdd(&g_count, 1u);
                const u32 target = (u32)(t + 1) * NCTA;
                while (*(volatile u32*)&g_count < target) __nanosleep(64);
                __threadfence();
            }
            __syncthreads();
        }
    }
}

// ---------------------------------------------------------------- CE loss (warp per batch row)
__global__ void __launch_bounds__(256)
ce_kernel(const int* __restrict__ labels, const void* __restrict__ maskp,
          const float* __restrict__ U, const float* __restrict__ b2)
{
    __shared__ float Us[H_ * C_];
    __shared__ float b2s[C_];
    __shared__ u32   flg_s[8];
    __shared__ float redce[8], redm[8];

    const int t = blockIdx.x;
    const int tid = threadIdx.x;
    const int lane = tid & 31, wid = tid >> 5;

    for (int i = tid; i < H_ * C_; i += 256) Us[i] = U[i];
    if (tid < C_) b2s[tid] = b2[tid];

    // mask encoding detection (int32 0/1, byte 0/1, float 0/1.0)
    const u32* mi = (const u32*)maskp;
    u32 fl = 0;
    for (int i = tid; i < (B_ * T_) / 4; i += 256) {
        u32 v = mi[i];
        if (v & ~1u)                     fl |= 1;
        if (v != 0u && v != 0x3F800000u) fl |= 2;
        if (v & 0xFEFEFEFEu)             fl |= 4;
    }
    #pragma unroll
    for (int off = 16; off; off >>= 1) fl |= __shfl_down_sync(0xffffffffu, fl, off);
    if (lane == 0) flg_s[wid] = fl;
    __syncthreads();
    if (tid == 0) { u32 a = 0; for (int w = 0; w < 8; ++w) a |= flg_s[w]; flg_s[0] = a; }
    __syncthreads();
    fl = flg_s[0];
    const int mode = (!(fl & 1)) ? 0 : ((!(fl & 4)) ? 1 : ((!(fl & 2)) ? 2 : 0));

    float sce = 0.0f, smv = 0.0f;
    for (int b = wid; b < B_; b += 8) {
        size_t base = ((size_t)(t + 1) * B_ + b) * ROWE + 52;
        float acc[C_];
        #pragma unroll
        for (int c = 0; c < C_; ++c) acc[c] = 0.0f;
        for (int h = lane; h < H_; h += 32) {
            float v = us2f(g_Ahi[base + h]) + us2f(g_Alo[base + h]);
            #pragma unroll
            for (int c = 0; c < C_; ++c) acc[c] += v * Us[h * C_ + c];
        }
        #pragma unroll
        for (int c = 0; c < C_; ++c) {
            #pragma unroll
            for (int off = 16; off; off >>= 1)
                acc[c] += __shfl_down_sync(0xffffffffu, acc[c], off);
        }
        if (lane == 0) {
            #pragma unroll
            for (int c = 0; c < C_; ++c) acc[c] += b2s[c];
            float mx = acc[0];
            #pragma unroll
            for (int c = 1; c < C_; ++c) mx = fmaxf(mx, acc[c]);
            float s = 0.0f;
            #pragma unroll
            for (int c = 0; c < C_; ++c) s += __expf(acc[c] - mx);
            float lse = mx + __logf(s);
            int lab = labels[b * T_ + t];
            lab = max(0, min(C_ - 1, lab));
            float ce = lse - acc[lab];
            const int j = b * T_ + t;
            float mk;
            if (mode == 0)      mk = ((const int*)maskp)[j] ? 1.0f : 0.0f;
            else if (mode == 1) mk = ((const unsigned char*)maskp)[j] ? 1.0f : 0.0f;
            else                mk = (((const float*)maskp)[j] != 0.0f) ? 1.0f : 0.0f;
            sce += ce * mk;
            smv += mk;
        }
    }
    if (lane == 0) { redce[wid] = sce; redm[wid] = smv; }
    __syncthreads();
    if (tid == 0) {
        float a = 0.0f, c = 0.0f;
        for (int w = 0; w < 8; ++w) { a += redce[w]; c += redm[w]; }
        g_partial_ce[t] = a;
        g_partial_cnt[t] = c;
    }
}

__global__ void fin_kernel(float* out) {
    float a = 0.0f, c = 0.0f;
    for (int t = 0; t < T_; ++t) { a += g_partial_ce[t]; c += g_partial_cnt[t]; }
    out[0] = a / c;
}

// ---------------------------------------------------------------- launch
extern "C" void kernel_launch(void* const* d_in, const int* in_sizes, int n_in,
                              void* d_out, int out_size)
{
    cudaFuncSetAttribute(lstm_main, cudaFuncAttributeMaxDynamicSharedMemorySize, SMEM_TOTAL);

    const int*   tokens = (const int*)  d_in[0];
    const int*   labels = (const int*)  d_in[1];
    const void*  mask   =               d_in[2];
    const float* emb    = (const float*)d_in[3];
    const float* Wx     = (const float*)d_in[4];
    const float* Wh     = (const float*)d_in[5];
    const float* b      = (const float*)d_in[6];
    const float* U      = (const float*)d_in[7];
    const float* b2     = (const float*)d_in[8];
    float*       out    = (float*)d_out;

    init_kernel<<<(B_ * H_ + 1023) / 1024, 1024>>>();
    prex_kernel<<<(T_ * B_ + 255) / 256, 256>>>(tokens, emb);
    lstm_main<<<NCTA, THREADS, SMEM_TOTAL>>>(Wx, Wh, b);
    ce_kernel<<<T_, 256>>>(labels, mask, U, b2);
    fin_kernel<<<1, 1>>>(out);
}

// round 14
// speedup vs baseline: 2.0353x; 1.0678x over previous
#include <cuda_runtime.h>
#include <cuda_bf16.h>
#include <cstdint>

// Problem constants
#define B_      1024
#define T_      120
#define E_      50
#define H_      300
#define C_      5
#define G_      1200
#define VOCAB_  50000

// Combined input row per (t,b): [0..49]=x, [50..51]=0, [52..351]=h  -> 352 elems
#define KTOT    352
#define ROWE    352           // global row elems (704 B, 16B aligned)
#define NST     11            // K stages of 32 elems
#define NBB     8
#define BR      128           // batch rows per CTA (M)
#define NSL     15
#define HC      20            // h cols per CTA
#define GC      80            // gate cols per CTA (N)
#define NCTA    120
#define THREADS 256

// SMEM: A ring = 4 slots x 2 planes x (128 rows x 80B stride, 64B data)
#define ASTAGE  10240u        // 128*80
#define OFF_A   0u            // ring: slot s hi at s*2*ASTAGE, lo at +ASTAGE
#define OFF_W   81920u        // 4 planes of 80*368: WH h0, WH h1, WL h0, WL h1
#define WPLANE  29440u
#define OFF_BIAS 199680u
#define SMEM_TOTAL (200064 + 1024)

typedef unsigned u32;

// ---------------------------------------------------------------- scratch
__device__ __align__(256) unsigned short g_Ahi[(size_t)(T_+1) * B_ * ROWE];
__device__ __align__(256) unsigned short g_Alo[(size_t)(T_+1) * B_ * ROWE];
__device__ float g_partial_ce[T_ * 4];
__device__ float g_partial_cnt[T_ * 4];
__device__ u32   g_count;

// ---------------------------------------------------------------- helpers
__device__ __forceinline__ float sigf(float x)  { return __fdividef(1.0f, 1.0f + __expf(-x)); }
__device__ __forceinline__ float tanh_f(float x){ return 2.0f * sigf(2.0f * x) - 1.0f; }

__device__ __forceinline__ u32 splitpack(float v) {
    __nv_bfloat16 h = __float2bfloat16(v);
    float fh = __bfloat162float(h);
    __nv_bfloat16 l = __float2bfloat16(v - fh);
    return (u32)__bfloat16_as_ushort(h) | ((u32)__bfloat16_as_ushort(l) << 16);
}
__device__ __forceinline__ float us2f(unsigned short u) {
    return __bfloat162float(__ushort_as_bfloat16(u));
}
__device__ __forceinline__ u32 smem_u32(const void* p) {
    u32 a; asm("{ .reg .u64 t; cvta.to.shared.u64 t, %1; cvt.u32.u64 %0, t; }" : "=r"(a) : "l"(p));
    return a;
}
// A-plane swizzled offset: row stride 80B (20 words -> conflict-free frag loads)
__device__ __forceinline__ u32 swz_a(u32 r, u32 kb) {
    return r * 80u + (kb ^ (((r >> 3) & 3u) << 4));
}
// W-plane swizzled offset: row stride 368B (as validated in R11/R13)
__device__ __forceinline__ u32 swz_w(u32 r, u32 kb) {
    return r * 368u + (kb ^ (((r >> 3) & 3u) << 4));
}
__device__ __forceinline__ void cpa16(u32 dst, const void* src) {
    asm volatile("cp.async.cg.shared.global [%0], [%1], 16;"
                 :: "r"(dst), "l"(__cvta_generic_to_global(src)) : "memory");
}
__device__ __forceinline__ void mma_bf16(float& d0, float& d1, float& d2, float& d3,
                                         u32 a0, u32 a1, u32 a2, u32 a3, u32 b0, u32 b1) {
    asm("mma.sync.aligned.m16n8k16.row.col.f32.bf16.bf16.f32 "
        "{%0,%1,%2,%3}, {%4,%5,%6,%7}, {%8,%9}, {%0,%1,%2,%3};"
        : "+f"(d0), "+f"(d1), "+f"(d2), "+f"(d3)
        : "r"(a0), "r"(a1), "r"(a2), "r"(a3), "r"(b0), "r"(b1));
}

// ---------------------------------------------------------------- init / precompute
__global__ void init_kernel() {
    int idx = blockIdx.x * blockDim.x + threadIdx.x;
    if (idx < B_ * H_) {                       // zero h-part of plane 0
        int b = idx / H_, h = idx % H_;
        size_t o = (size_t)b * ROWE + 52 + h;
        g_Ahi[o] = 0; g_Alo[o] = 0;
    }
    if (idx == 0) g_count = 0u;
}

__global__ void __launch_bounds__(256)
prex_kernel(const int* __restrict__ tokens, const float* __restrict__ emb) {
    int idx = blockIdx.x * 256 + threadIdx.x;
    if (idx >= T_ * B_) return;
    int b = idx % B_, t = idx / B_;
    const float* er = emb + (size_t)tokens[b * T_ + t] * E_;
    size_t base = ((size_t)t * B_ + b) * ROWE;
    #pragma unroll 5
    for (int e = 0; e < E_; ++e) {
        u32 pk = splitpack(er[e]);
        g_Ahi[base + e] = (unsigned short)(pk & 0xFFFFu);
        g_Alo[base + e] = (unsigned short)(pk >> 16);
    }
    g_Ahi[base + 50] = 0; g_Ahi[base + 51] = 0;
    g_Alo[base + 50] = 0; g_Alo[base + 51] = 0;
}

// ---------------------------------------------------------------- main LSTM (HMMA bf16x3, pipelined staging)
__global__ void __launch_bounds__(THREADS, 1)
lstm_main(const float* __restrict__ Wx, const float* __restrict__ Wh,
          const float* __restrict__ bias)
{
    extern __shared__ char smem_raw[];
    char* sm = (char*)(((uintptr_t)smem_raw + 1023) & ~(uintptr_t)1023);
    const u32 sb = smem_u32(sm);
    float* bias_sm = (float*)(sm + OFF_BIAS);

    const int tid  = threadIdx.x;
    const int wid  = tid >> 5;
    const int lane = tid & 31;
    const int g    = lane >> 2;
    const int tg   = lane & 3;
    const int rg   = wid & 3;        // row group
    const int nh   = wid >> 2;       // N half
    const int R0   = rg * 32;
    const int bb   = blockIdx.x / NSL;
    const int sl   = blockIdx.x % NSL;
    const int b0   = bb * BR;
    const int h0   = sl * HC;
    const int r    = tid & 127;      // staged batch row
    const int pp   = tid >> 7;       // 16-elem half within stage

    // ---- one-time: W hi/lo tiles (K-half planes), swizzled (validated layout)
    for (int half = 0; half < 2; ++half) {
        char* WHp = sm + OFF_W + (u32)half * WPLANE;
        char* WLp = sm + OFF_W + 2u * WPLANE + (u32)half * WPLANE;
        for (int idx = tid; idx < GC * 184; idx += THREADS) {
            int n = idx / 184, ke = idx % 184;
            int k = half * 176 + ke;
            float v = 0.0f;
            if (ke < 176) {
                int col = (n & 3) * H_ + h0 + (n >> 2);
                if (k < 50)                   v = Wx[k * G_ + col];
                else if (k >= 52 && k < KTOT) v = Wh[(k - 52) * G_ + col];
            }
            u32 pk = splitpack(v);
            u32 off = swz_w((u32)n, (u32)ke * 2u);
            *(unsigned short*)(WHp + off) = (unsigned short)(pk & 0xFFFFu);
            *(unsigned short*)(WLp + off) = (unsigned short)(pk >> 16);
        }
    }
    for (int n = tid; n < GC; n += THREADS)
        bias_sm[n] = bias[(n & 3) * H_ + h0 + (n >> 2)];
    __syncthreads();

    float cst[2][5];
    #pragma unroll
    for (int mt = 0; mt < 2; ++mt)
        #pragma unroll
        for (int nt = 0; nt < 5; ++nt) cst[mt][nt] = 0.0f;

    const u32 d0off = swz_a((u32)r, (u32)(pp * 32));
    const u32 d1off = swz_a((u32)r, (u32)(pp * 32 + 16));

    for (int t = 0; t < T_; ++t) {
        const unsigned short* rowHi = g_Ahi + ((size_t)t * B_ + b0 + r) * ROWE + pp * 16;
        const unsigned short* rowLo = g_Alo + ((size_t)t * B_ + b0 + r) * ROWE + pp * 16;

        // accumulators = bias
        float d[2][5][4];
        #pragma unroll
        for (int nt = 0; nt < 5; ++nt) {
            int ntg = nh * 5 + nt;
            float bv0 = bias_sm[ntg * 8 + 2 * tg];
            float bv1 = bias_sm[ntg * 8 + 2 * tg + 1];
            #pragma unroll
            for (int mt = 0; mt < 2; ++mt) {
                d[mt][nt][0] = bv0; d[mt][nt][1] = bv1;
                d[mt][nt][2] = bv0; d[mt][nt][3] = bv1;
            }
        }

        // ---- prologue: issue stages 0..2
        #pragma unroll
        for (int st = 0; st < 3; ++st) {
            u32 slot = sb + OFF_A + (u32)(st & 3) * (2u * ASTAGE);
            cpa16(slot + d0off, rowHi + st * 32);
            cpa16(slot + d1off, rowHi + st * 32 + 8);
            cpa16(slot + ASTAGE + d0off, rowLo + st * 32);
            cpa16(slot + ASTAGE + d1off, rowLo + st * 32 + 8);
            asm volatile("cp.async.commit_group;" ::: "memory");
        }

        #pragma unroll 1
        for (int st = 0; st < NST; ++st) {
            asm volatile("cp.async.wait_group 2;" ::: "memory");
            __syncthreads();
            if (st < NST - 3) {
                int sn = st + 3;
                u32 slot = sb + OFF_A + (u32)(sn & 3) * (2u * ASTAGE);
                cpa16(slot + d0off, rowHi + sn * 32);
                cpa16(slot + d1off, rowHi + sn * 32 + 8);
                cpa16(slot + ASTAGE + d0off, rowLo + sn * 32);
                cpa16(slot + ASTAGE + d1off, rowLo + sn * 32 + 8);
            }
            asm volatile("cp.async.commit_group;" ::: "memory");

            const char* Ah = sm + OFF_A + (u32)(st & 3) * (2u * ASTAGE);
            const char* Al = Ah + ASTAGE;

            #pragma unroll
            for (int kl = 0; kl < 2; ++kl) {
                const int kk  = st * 2 + kl;
                const int half = (kk >= 11);
                const int kcH  = kk - half * 11;
                const char* WHp = sm + OFF_W + (u32)half * WPLANE;
                const char* WLp = sm + OFF_W + 2u * WPLANE + (u32)half * WPLANE;
                const u32 cb  = (u32)(kl * 32 + 4 * tg);
                const u32 cbW = (u32)(kcH * 32 + 4 * tg);

                u32 ah[2][4], al[2][4];
                #pragma unroll
                for (int mt = 0; mt < 2; ++mt) {
                    u32 ra = (u32)(R0 + mt * 16 + g), rb = ra + 8u;
                    u32 oa0 = swz_a(ra, cb),       ob0 = swz_a(rb, cb);
                    u32 oa1 = swz_a(ra, cb + 16u), ob1 = swz_a(rb, cb + 16u);
                    ah[mt][0] = *(const u32*)(Ah + oa0);
                    ah[mt][1] = *(const u32*)(Ah + ob0);
                    ah[mt][2] = *(const u32*)(Ah + oa1);
                    ah[mt][3] = *(const u32*)(Ah + ob1);
                    al[mt][0] = *(const u32*)(Al + oa0);
                    al[mt][1] = *(const u32*)(Al + ob0);
                    al[mt][2] = *(const u32*)(Al + oa1);
                    al[mt][3] = *(const u32*)(Al + ob1);
                }
                #pragma unroll
                for (int nt = 0; nt < 5; ++nt) {
                    u32 na = (u32)((nh * 5 + nt) * 8 + g);
                    u32 o0 = swz_w(na, cbW), o1 = swz_w(na, cbW + 16u);
                    u32 bh0 = *(const u32*)(WHp + o0), bh1 = *(const u32*)(WHp + o1);
                    u32 bl0 = *(const u32*)(WLp + o0), bl1 = *(const u32*)(WLp + o1);
                    #pragma unroll
                    for (int mt = 0; mt < 2; ++mt) {
                        mma_bf16(d[mt][nt][0], d[mt][nt][1], d[mt][nt][2], d[mt][nt][3],
                                 ah[mt][0], ah[mt][1], ah[mt][2], ah[mt][3], bh0, bh1);
                        mma_bf16(d[mt][nt][0], d[mt][nt][1], d[mt][nt][2], d[mt][nt][3],
                                 ah[mt][0], ah[mt][1], ah[mt][2], ah[mt][3], bl0, bl1);
                        mma_bf16(d[mt][nt][0], d[mt][nt][1], d[mt][nt][2], d[mt][nt][3],
                                 al[mt][0], al[mt][1], al[mt][2], al[mt][3], bh0, bh1);
                    }
                }
            }
        }

        // ---- epilogue: pair-exchange gates, LSTM cell, write hi/lo h
        const int odd = lane & 1;
        #pragma unroll
        for (int mt = 0; mt < 2; ++mt) {
            #pragma unroll
            for (int nt = 0; nt < 5; ++nt) {
                int ntg = nh * 5 + nt;
                float e0 = __shfl_xor_sync(0xffffffffu, d[mt][nt][0], 1);
                float e1 = __shfl_xor_sync(0xffffffffu, d[mt][nt][1], 1);
                float e2 = __shfl_xor_sync(0xffffffffu, d[mt][nt][2], 1);
                float e3 = __shfl_xor_sync(0xffffffffu, d[mt][nt][3], 1);
                float zi, zj, zf, zo; int row;
                if (!odd) { zi = d[mt][nt][0]; zj = d[mt][nt][1]; zf = e0; zo = e1;
                            row = R0 + mt * 16 + g; }
                else      { zi = e2; zj = e3; zf = d[mt][nt][2]; zo = d[mt][nt][3];
                            row = R0 + mt * 16 + g + 8; }
                float ig = sigf(zi);
                float jg = tanh_f(zj);
                float fg = sigf(zf + 1.0f);      // FORGET_BIAS
                float og = sigf(zo);
                float cn = fg * cst[mt][nt] + ig * jg;
                cst[mt][nt] = cn;
                float hn = og * tanh_f(cn);
                int hcol = h0 + ntg * 2 + (tg >> 1);
                size_t o = ((size_t)(t + 1) * B_ + b0 + row) * ROWE + 52 + hcol;
                u32 pk = splitpack(hn);
                g_Ahi[o] = (unsigned short)(pk & 0xFFFFu);
                g_Alo[o] = (unsigned short)(pk >> 16);
            }
        }

        // ---- grid barrier (120 co-resident CTAs, monotonic ticket)
        if (t + 1 < T_) {
            __threadfence();
            __syncthreads();
            if (tid == 0) {
                atomicAdd(&g_count, 1u);
                const u32 target = (u32)(t + 1) * NCTA;
                while (*(volatile u32*)&g_count < target) __nanosleep(64);
                __threadfence();
            }
            __syncthreads();
        }
    }
}

// ---------------------------------------------------------------- CE loss (480 blocks, coalesced)
__global__ void __launch_bounds__(256)
ce_kernel(const int* __restrict__ labels, const void* __restrict__ maskp,
          const float* __restrict__ U, const float* __restrict__ b2)
{
    __shared__ float Us[H_ * C_];
    __shared__ float b2s[C_];
    __shared__ u32   flg_s[8];
    __shared__ float redce[8], redm[8];

    const int t   = blockIdx.x >> 2;
    const int q   = blockIdx.x & 3;
    const int tid = threadIdx.x;
    const int lane = tid & 31, wid = tid >> 5;

    for (int i = tid; i < H_ * C_; i += 256) Us[i] = U[i];
    if (tid < C_) b2s[tid] = b2[tid];

    // mask encoding detection (int32 0/1, byte 0/1, float 0/1.0)
    const u32* mi = (const u32*)maskp;
    u32 fl = 0;
    for (int i = tid; i < (B_ * T_) / 4; i += 256) {
        u32 v = mi[i];
        if (v & ~1u)                     fl |= 1;
        if (v != 0u && v != 0x3F800000u) fl |= 2;
        if (v & 0xFEFEFEFEu)             fl |= 4;
    }
    #pragma unroll
    for (int off = 16; off; off >>= 1) fl |= __shfl_down_sync(0xffffffffu, fl, off);
    if (lane == 0) flg_s[wid] = fl;
    __syncthreads();
    if (tid == 0) { u32 a = 0; for (int w = 0; w < 8; ++w) a |= flg_s[w]; flg_s[0] = a; }
    __syncthreads();
    fl = flg_s[0];
    const int mode = (!(fl & 1)) ? 0 : ((!(fl & 4)) ? 1 : ((!(fl & 2)) ? 2 : 0));

    float sce = 0.0f, smv = 0.0f;
    for (int br = 0; br < 32; ++br) {
        const int b = q * 256 + wid * 32 + br;
        size_t base = ((size_t)(t + 1) * B_ + b) * ROWE + 52;
        float acc[C_];
        #pragma unroll
        for (int c = 0; c < C_; ++c) acc[c] = 0.0f;
        #pragma unroll
        for (int i = 0; i < 5; ++i) {
            int h = i * 64 + lane * 2;
            if (h < H_) {
                u32 vh = *(const u32*)(g_Ahi + base + h);
                u32 vl = *(const u32*)(g_Alo + base + h);
                float v0 = us2f((unsigned short)(vh & 0xFFFFu)) + us2f((unsigned short)(vl & 0xFFFFu));
                float v1 = us2f((unsigned short)(vh >> 16))     + us2f((unsigned short)(vl >> 16));
                #pragma unroll
                for (int c = 0; c < C_; ++c)
                    acc[c] += v0 * Us[h * C_ + c] + v1 * Us[(h + 1) * C_ + c];
            }
        }
        #pragma unroll
        for (int c = 0; c < C_; ++c) {
            #pragma unroll
            for (int off = 16; off; off >>= 1)
                acc[c] += __shfl_down_sync(0xffffffffu, acc[c], off);
        }
        if (lane == 0) {
            #pragma unroll
            for (int c = 0; c < C_; ++c) acc[c] += b2s[c];
            float mx = acc[0];
            #pragma unroll
            for (int c = 1; c < C_; ++c) mx = fmaxf(mx, acc[c]);
            float s = 0.0f;
            #pragma unroll
            for (int c = 0; c < C_; ++c) s += __expf(acc[c] - mx);
            float lse = mx + __logf(s);
            int lab = labels[b * T_ + t];
            lab = max(0, min(C_ - 1, lab));
            float ce = lse - acc[lab];
            const int j = b * T_ + t;
            float mk;
            if (mode == 0)      mk = ((const int*)maskp)[j] ? 1.0f : 0.0f;
            else if (mode == 1) mk = ((const unsigned char*)maskp)[j] ? 1.0f : 0.0f;
            else                mk = (((const float*)maskp)[j] != 0.0f) ? 1.0f : 0.0f;
            sce += ce * mk;
            smv += mk;
        }
    }
    if (lane == 0) { redce[wid] = sce; redm[wid] = smv; }
    __syncthreads();
    if (tid == 0) {
        float a = 0.0f, c = 0.0f;
        for (int w = 0; w < 8; ++w) { a += redce[w]; c += redm[w]; }
        g_partial_ce[t * 4 + q]  = a;
        g_partial_cnt[t * 4 + q] = c;
    }
}

__global__ void fin_kernel(float* out) {
    float a = 0.0f, c = 0.0f;
    for (int i = 0; i < T_ * 4; ++i) { a += g_partial_ce[i]; c += g_partial_cnt[i]; }
    out[0] = a / c;
}

// ---------------------------------------------------------------- launch
extern "C" void kernel_launch(void* const* d_in, const int* in_sizes, int n_in,
                              void* d_out, int out_size)
{
    cudaFuncSetAttribute(lstm_main, cudaFuncAttributeMaxDynamicSharedMemorySize, SMEM_TOTAL);

    const int*   tokens = (const int*)  d_in[0];
    const int*   labels = (const int*)  d_in[1];
    const void*  mask   =               d_in[2];
    const float* emb    = (const float*)d_in[3];
    const float* Wx     = (const float*)d_in[4];
    const float* Wh     = (const float*)d_in[5];
    const float* b      = (const float*)d_in[6];
    const float* U      = (const float*)d_in[7];
    const float* b2     = (const float*)d_in[8];
    float*       out    = (float*)d_out;

    init_kernel<<<(B_ * H_ + 1023) / 1024, 1024>>>();
    prex_kernel<<<(T_ * B_ + 255) / 256, 256>>>(tokens, emb);
    lstm_main<<<NCTA, THREADS, SMEM_TOTAL>>>(Wx, Wh, b);
    ce_kernel<<<T_ * 4, 256>>>(labels, mask, U, b2);
    fin_kernel<<<1, 1>>>(out);
}